// round 16
// baseline (speedup 1.0000x reference)
#include <cuda_runtime.h>
#include <math.h>

#define NN    100000
#define BB    32
#define NPERK 3125
#define NT    100032          // NN + BB   (NN % 32 == 0, NT % 64 == 0)
#define EE    200000
#define ET    500032          // EE + 2*NN + NT
#define E2    (EE + NN)       // 300000: random + glb->node (self-loops analytic)

// ---------------- scratch (device globals; no allocations) ----------------
__device__ __align__(16) float g_xh1 [NT * 128];
__device__ __align__(16) float g_agg1[NT * 128];   // edge-only sums (self added in g2pre)
__device__ __align__(16) float g_xh2 [NT * 64];
__device__ float g_s1[NT * 2], g_d1[NT * 2], g_den1[NT * 2];
__device__ float g_s2[NT];
__device__ __align__(8) float2 g_dd2[NT];          // {d2, den2}
// fused feat->xh1 weights (precomputed each launch by k_fuse)
__device__ __align__(16) float g_F [64 * 128];
__device__ __align__(16) float g_bF[128];
__device__ __align__(16) float g_gx[128];          // glb-node xh1 row
__device__ float g_gl[6];                          // glb s1h0,s1h1,d1h0,d1h1,den1h0,den1h1

// ---------------- helpers ----------------
typedef unsigned long long u64;
__device__ __forceinline__ u64 pk2(float lo, float hi) {
    u64 r; asm("mov.b64 %0,{%1,%2};" : "=l"(r) : "f"(lo), "f"(hi)); return r;
}
__device__ __forceinline__ u64 bc2(float v) { return pk2(v, v); }
__device__ __forceinline__ void upk2(u64 v, float& lo, float& hi) {
    asm("mov.b64 {%0,%1},%2;" : "=f"(lo), "=f"(hi) : "l"(v));
}
__device__ __forceinline__ void fma2(u64& d, u64 a, u64 b) {
    asm("fma.rn.f32x2 %0, %1, %2, %0;" : "+l"(d) : "l"(a), "l"(b));
}
__device__ __forceinline__ float lrelu(float a) { return a > 0.f ? a : 0.2f * a; }

__device__ __forceinline__ float wsum(float v) {
    #pragma unroll
    for (int o = 16; o; o >>= 1) v += __shfl_xor_sync(0xffffffffu, v, o);
    return v;
}
__device__ __forceinline__ float hsum16(float v) {
    #pragma unroll
    for (int o = 8; o; o >>= 1) v += __shfl_xor_sync(0xffffffffu, v, o);
    return v;
}

// full edge list (for att output): src=[ei0,glb,ids,loop], dst=[ei1,ids,glb,loop]
__device__ __forceinline__ void edge_sd(int e, const int* __restrict__ ei, int& s, int& d) {
    if (e < EE)             { s = ei[e];               d = ei[EE + e]; }
    else if (e < EE + NN)   { int i = e - EE;          s = NN + i / NPERK; d = i; }
    else if (e < EE + 2*NN) { int i = e - EE - NN;     s = i; d = NN + i / NPERK; }
    else                    { int i = e - EE - 2*NN;   s = i; d = i; }
}
// light edges without self-loops: random + glb->node (all dst < NN)
__device__ __forceinline__ void edge2(int e, const int* __restrict__ ei, int& s, int& d) {
    if (e < EE) { s = ei[e]; d = ei[EE + e]; }
    else        { int i = e - EE; s = NN + i / NPERK; d = i; }
}

// =========== weight fusion: F = fold(ltW/lvW, gW, W1), bF, glb row ========
__global__ void k_fuse(const float* __restrict__ ltW, const float* __restrict__ ltWb,
                       const float* __restrict__ lvW, const float* __restrict__ lvWb,
                       const float* __restrict__ gW,  const float* __restrict__ gb,
                       const float* __restrict__ glbn, const float* __restrict__ W1,
                       const float* __restrict__ asr, const float* __restrict__ ads)
{
    int b = blockIdx.x, c = threadIdx.x;
    if (b < 64) {
        __shared__ float H[64];
        if (c < 64) {
            float acc = 0.f;
            if (b < 39) { for (int m = 0; m < 64; m++) acc += ltW[b * 64 + m] * gW[(64 + m) * 64 + c]; }
            else { int j = b - 39; for (int m = 0; m < 64; m++) acc += lvW[j * 64 + m] * gW[m * 64 + c]; }
            H[c] = acc;
        }
        __syncthreads();
        float f = 0.f;
        for (int a = 0; a < 64; a++) f += H[a] * W1[a * 128 + c];
        g_F[b * 128 + c] = f;
    } else {
        __shared__ float Hb[64], GX[128];
        if (c < 64) {
            float acc = gb[c];
            for (int m = 0; m < 64; m++) acc += lvWb[m] * gW[m * 64 + c];
            for (int m = 0; m < 64; m++) acc += ltWb[m] * gW[(64 + m) * 64 + c];
            Hb[c] = acc;
        }
        __syncthreads();
        float bf = 0.f, gx = 0.f;
        for (int a = 0; a < 64; a++) {
            bf += Hb[a] * W1[a * 128 + c];
            gx += glbn[a] * W1[a * 128 + c];
        }
        g_bF[c] = bf;
        g_gx[c] = gx;
        GX[c] = gx;
        __syncthreads();
        if (c < 32) {
            int l = c;
            float4 av = ((const float4*)asr)[l];
            float4 dv = ((const float4*)ads)[l];
            float ps = GX[4*l] * av.x + GX[4*l+1] * av.y + GX[4*l+2] * av.z + GX[4*l+3] * av.w;
            float pd = GX[4*l] * dv.x + GX[4*l+1] * dv.y + GX[4*l+2] * dv.z + GX[4*l+3] * dv.w;
            ps = hsum16(ps); pd = hsum16(pd);
            if (l == 0)  { g_gl[0] = ps; g_gl[2] = pd; g_gl[4] = expf(lrelu(ps + pd)); }
            if (l == 16) { g_gl[1] = ps; g_gl[3] = pd; g_gl[5] = expf(lrelu(ps + pd)); }
        }
    }
}

// =========== fused node pipeline: LN -> xh1 = LNfeat @ F + bF =============
// also zeroes this block's agg1 rows (base for the edge atomics)
#define SF 34
__global__ void __launch_bounds__(128)
k_nodeg1(const float* __restrict__ feat,
         const float* __restrict__ ltg, const float* __restrict__ ltb,
         const float* __restrict__ lvg, const float* __restrict__ lvb,
         const float* __restrict__ asr, const float* __restrict__ ads)
{
    __shared__ float shF[64 * SF];
    int tid = threadIdx.x, wp = tid >> 5, l = tid & 31;
    int n0 = blockIdx.x * 32;
    int nb = wp * 8;

    // zero agg1 rows for this block's 32 nodes (edge-sum base)
    {
        float4 z = make_float4(0.f, 0.f, 0.f, 0.f);
        float4* dst = (float4*)(g_agg1 + n0 * 128);
        #pragma unroll
        for (int t = 0; t < 8; t++) dst[t * 128 + tid] = z;
    }

    if (n0 >= NN) {                    // last block: pure glb nodes
        for (int t = tid; t < 32 * 32; t += 128) {
            int nl = t >> 5, l4 = t & 31;
            ((float4*)(g_xh1 + (NN + nl) * 128))[l4] = ((const float4*)g_gx)[l4];
        }
        if (tid < 32) {
            int n = NN + tid;
            g_s1[2*n] = g_gl[0]; g_s1[2*n+1] = g_gl[1];
            g_d1[2*n] = g_gl[2]; g_d1[2*n+1] = g_gl[3];
            g_den1[2*n] = g_gl[4]; g_den1[2*n+1] = g_gl[5];
        }
        return;
    }

    for (int t = tid; t < 32 * 64; t += 128) {
        int nl = t >> 6, c = t & 63;
        shF[c * SF + nl] = feat[(n0 + nl) * 64 + c];
    }
    __syncthreads();

    // ---- layernorm per node (round-6 wsum order), 8 nodes/warp ----
    #pragma unroll
    for (int i = 0; i < 8; i++) {
        int nl = nb + i;
        float f0 = shF[l * SF + nl];
        float f1 = shF[(32 + l) * SF + nl];
        int k1 = l + 32;
        float ts = f0      + (k1 < 39 ? f1      : 0.f);
        float tq = f0 * f0 + (k1 < 39 ? f1 * f1 : 0.f);
        float vs = (k1 >= 39 ? f1      : 0.f);
        float vq = (k1 >= 39 ? f1 * f1 : 0.f);
        ts = wsum(ts); tq = wsum(tq); vs = wsum(vs); vq = wsum(vq);
        float mt = ts * (1.f / 39.f);
        float rt = rsqrtf(tq * (1.f / 39.f) - mt * mt + 1e-5f);
        float mv = vs * (1.f / 25.f);
        float rv = rsqrtf(vq * (1.f / 25.f) - mv * mv + 1e-5f);
        float a = (f0 - mt) * rt * ltg[l] + ltb[l];
        float b;
        if (k1 < 39) b = (f1 - mt) * rt * ltg[k1] + ltb[k1];
        else { int j = k1 - 39; b = (f1 - mv) * rv * lvg[j] + lvb[j]; }
        shF[l * SF + nl] = a; shF[k1 * SF + nl] = b;
    }
    __syncwarp();

    // ---- xh1 = LNfeat @ F + bF; logits + den1 self ----
    {
        float4 bf = ((const float4*)g_bF)[l];
        u64 ox[4], oy[4], oz[4], ow[4];
        #pragma unroll
        for (int q = 0; q < 4; q++) {
            ox[q] = bc2(bf.x); oy[q] = bc2(bf.y);
            oz[q] = bc2(bf.z); ow[q] = bc2(bf.w);
        }
        for (int k = 0; k < 64; k++) {
            float4 w = ((const float4*)(g_F + k * 128))[l];
            u64 w0 = bc2(w.x), w1 = bc2(w.y), w2 = bc2(w.z), w3 = bc2(w.w);
            #pragma unroll
            for (int q = 0; q < 4; q++) {
                u64 sp = *(const u64*)&shF[k * SF + nb + 2 * q];
                fma2(ox[q], sp, w0); fma2(oy[q], sp, w1);
                fma2(oz[q], sp, w2); fma2(ow[q], sp, w3);
            }
        }
        float4 av = ((const float4*)asr)[l];
        float4 dv = ((const float4*)ads)[l];
        #pragma unroll
        for (int i = 0; i < 8; i++) {
            int q = i >> 1;
            float x0, x1, y0, y1, z0, z1, u0, u1;
            upk2(ox[q], x0, x1); upk2(oy[q], y0, y1);
            upk2(oz[q], z0, z1); upk2(ow[q], u0, u1);
            float a = (i & 1) ? x1 : x0;
            float b = (i & 1) ? y1 : y0;
            float c = (i & 1) ? z1 : z0;
            float e = (i & 1) ? u1 : u0;
            int n = n0 + nb + i;
            float ps = hsum16(a * av.x + b * av.y + c * av.z + e * av.w);
            float pd = hsum16(a * dv.x + b * dv.y + c * dv.z + e * dv.w);
            ((float4*)(g_xh1 + n * 128))[l] = make_float4(a, b, c, e);
            if (l == 0) {
                g_s1[2 * n] = ps; g_d1[2 * n] = pd;
                g_den1[2 * n] = expf(lrelu(ps + pd));
            }
            if (l == 16) {
                g_s1[2 * n + 1] = ps; g_d1[2 * n + 1] = pd;
                g_den1[2 * n + 1] = expf(lrelu(ps + pd));
            }
        }
    }
}

// =========== GAT1 denominator: edge (2/thread) + glb ======================
#define NBDE2 ((E2 + 511) / 512)        // 586 edge blocks
#define DP 32
#define DC ((NPERK + DP - 1) / DP)      // 98
__global__ void k_g1den(const int* __restrict__ ei) {
    int bid = blockIdx.x;
    if (bid < NBDE2) {
        int e = bid * 512 + threadIdx.x;
        if (e + 256 < E2) {
            int sa, da, sb, db;
            edge2(e,       ei, sa, da);
            edge2(e + 256, ei, sb, db);
            float2 sva = *(const float2*)&g_s1[2 * sa];
            float2 dva = *(const float2*)&g_d1[2 * da];
            float2 svb = *(const float2*)&g_s1[2 * sb];
            float2 dvb = *(const float2*)&g_d1[2 * db];
            atomicAdd((float2*)&g_den1[2 * da],
                      make_float2(expf(lrelu(sva.x + dva.x)), expf(lrelu(sva.y + dva.y))));
            atomicAdd((float2*)&g_den1[2 * db],
                      make_float2(expf(lrelu(svb.x + dvb.x)), expf(lrelu(svb.y + dvb.y))));
        } else if (e < E2) {
            int sa, da;
            edge2(e, ei, sa, da);
            float2 sva = *(const float2*)&g_s1[2 * sa];
            float2 dva = *(const float2*)&g_d1[2 * da];
            atomicAdd((float2*)&g_den1[2 * da],
                      make_float2(expf(lrelu(sva.x + dva.x)), expf(lrelu(sva.y + dva.y))));
        }
    } else {
        int b = bid - NBDE2;
        int g = b / DP, p = b % DP;
        int beg = g * NPERK + p * DC;
        int end = min(beg + DC, (g + 1) * NPERK);
        float dh0 = g_d1[(NN + g) * 2], dh1 = g_d1[(NN + g) * 2 + 1];
        float a0 = 0.f, a1 = 0.f;
        for (int i = beg + threadIdx.x; i < end; i += 256) {
            a0 += expf(lrelu(g_s1[2 * i]     + dh0));
            a1 += expf(lrelu(g_s1[2 * i + 1] + dh1));
        }
        a0 = wsum(a0); a1 = wsum(a1);
        __shared__ float sd[2];
        if (threadIdx.x < 2) sd[threadIdx.x] = 0.f;
        __syncthreads();
        if ((threadIdx.x & 31) == 0) { atomicAdd(&sd[0], a0); atomicAdd(&sd[1], a1); }
        __syncthreads();
        if (threadIdx.x < 2) atomicAdd(&g_den1[(NN + g) * 2 + threadIdx.x], sd[threadIdx.x]);
    }
}

// =========== GAT1 aggregation: edge (4/warp, MLP 4) + glb =================
#define NBAE4 (E2 / 32)                 // 9375 exact
#define AP 64
#define AC ((NPERK + AP - 1) / AP)      // 49
__global__ void k_g1agg(const int* __restrict__ ei) {
    int bid = blockIdx.x;
    if (bid < NBAE4) {
        int wp = threadIdx.x >> 5, l = threadIdx.x & 31;
        int h = l >> 4;
        int e0 = bid * 32 + wp * 4;
        int s[4], d[4];
        #pragma unroll
        for (int j = 0; j < 4; j++) edge2(e0 + j, ei, s[j], d[j]);
        float w[4];
        #pragma unroll
        for (int j = 0; j < 4; j++)
            w[j] = expf(lrelu(g_s1[s[j] * 2 + h] + g_d1[d[j] * 2 + h]))
                 / (g_den1[d[j] * 2 + h] + 1e-16f);
        float4 v[4];
        #pragma unroll
        for (int j = 0; j < 4; j++) v[j] = ((const float4*)g_xh1)[s[j] * 32 + l];
        #pragma unroll
        for (int j = 0; j < 4; j++) {
            v[j].x *= w[j]; v[j].y *= w[j]; v[j].z *= w[j]; v[j].w *= w[j];
            atomicAdd(((float4*)g_agg1) + d[j] * 32 + l, v[j]);
        }
    } else {
        int q = (bid - NBAE4) * 2 + (threadIdx.x >> 7);
        int g = q / AP, p = q % AP;
        int beg = g * NPERK + p * AC;
        int end = min(beg + AC, (g + 1) * NPERK);
        int c = threadIdx.x & 127, h = c >> 6;
        float dh  = g_d1[(NN + g) * 2 + h];
        float den = g_den1[(NN + g) * 2 + h] + 1e-16f;
        float acc = 0.f;
        int s = beg;
        for (; s + 3 < end; s += 4) {
            float w0 = expf(lrelu(g_s1[2 * s + h]     + dh)) / den;
            float w1 = expf(lrelu(g_s1[2 * (s+1) + h] + dh)) / den;
            float w2 = expf(lrelu(g_s1[2 * (s+2) + h] + dh)) / den;
            float w3 = expf(lrelu(g_s1[2 * (s+3) + h] + dh)) / den;
            float x0 = g_xh1[s * 128 + c];
            float x1 = g_xh1[(s+1) * 128 + c];
            float x2 = g_xh1[(s+2) * 128 + c];
            float x3 = g_xh1[(s+3) * 128 + c];
            acc += w0 * x0 + w1 * x1 + w2 * x2 + w3 * x3;
        }
        for (; s < end; s++)
            acc += expf(lrelu(g_s1[2 * s + h] + dh)) / den * g_xh1[s * 128 + c];
        atomicAdd(&g_agg1[(NN + g) * 128 + c], acc);
    }
}

// =========== GAT2 transform: + self-loop term, transposed smem f32x2 ======
#define SH 66
__global__ void __launch_bounds__(256)
k_g2pre(const float* __restrict__ b1, const float* __restrict__ W2,
        const float* __restrict__ as2, const float* __restrict__ ad2,
        const float* __restrict__ b2, float* __restrict__ out)
{
    __shared__ float shH[128 * SH];    // relu(agg1 + w_self*xh1 + b1)  [ch][node]
    __shared__ float shWS[128];        // w_self per (node, head)
    int tid = threadIdx.x, wp = tid >> 5, l = tid & 31;
    int n0 = blockIdx.x * 64;
    int nb = wp * 8;

    if (blockIdx.x == 0) {             // seed out[0:2048] = b2 (g2out adds into it)
        for (int i = tid; i < BB * 64; i += 256) out[i] = b2[i & 63];
    }

    if (tid < 128) {                   // w_self = exp(lrelu(s+d)) / den
        int node = tid >> 1, h = tid & 1;
        int gn = n0 + node;
        float ex = expf(lrelu(g_s1[2 * gn + h] + g_d1[2 * gn + h]));
        shWS[node * 2 + h] = ex / (g_den1[2 * gn + h] + 1e-16f);
    }
    __syncthreads();

    for (int t = tid; t < 64 * 128; t += 256) {
        int nl = t >> 7, c = t & 127;
        int gn = n0 + nl;
        float v = fmaxf(g_agg1[gn * 128 + c]
                        + shWS[nl * 2 + (c >> 6)] * g_xh1[gn * 128 + c]
                        + b1[c], 0.f);
        shH[c * SH + nl] = v;
    }
    __syncthreads();

    u64 oa[4], ob[4];
    #pragma unroll
    for (int q = 0; q < 4; q++) { oa[q] = 0; ob[q] = 0; }
    for (int k = 0; k < 128; k++) {
        float2 w = ((const float2*)(W2 + k * 64))[l];
        u64 wx = bc2(w.x), wy = bc2(w.y);
        #pragma unroll
        for (int q = 0; q < 4; q++) {
            u64 sp = *(const u64*)&shH[k * SH + nb + 2 * q];
            fma2(oa[q], sp, wx); fma2(ob[q], sp, wy);
        }
    }
    float2 sa = ((const float2*)as2)[l];
    float2 da = ((const float2*)ad2)[l];
    #pragma unroll
    for (int i = 0; i < 8; i++) {
        int q = i >> 1;
        float a0, a1, b0v, b1v;
        upk2(oa[q], a0, a1); upk2(ob[q], b0v, b1v);
        float a = (i & 1) ? a1 : a0;
        float b = (i & 1) ? b1v : b0v;
        int n = n0 + nb + i;
        float ps = wsum(a * sa.x + b * sa.y);
        float pd = wsum(a * da.x + b * da.y);
        ((float2*)(g_xh2 + n * 64))[l] = make_float2(a, b);
        if (l == 0) {
            g_s2[n] = ps;
            g_dd2[n] = make_float2(pd, expf(lrelu(ps + pd)));  // {d2, den2 self base}
        }
    }
}

// =========== GAT2 denominator: edge (2/thread) + glb ======================
__global__ void k_g2den(const int* __restrict__ ei) {
    int bid = blockIdx.x;
    if (bid < NBDE2) {
        int e = bid * 512 + threadIdx.x;
        if (e + 256 < E2) {
            int sa, da, sb, db;
            edge2(e,       ei, sa, da);
            edge2(e + 256, ei, sb, db);
            float s0 = g_s2[sa], d0 = g_dd2[da].x;
            float s1v = g_s2[sb], d1v = g_dd2[db].x;
            atomicAdd(&g_dd2[da].y, expf(lrelu(s0 + d0)));
            atomicAdd(&g_dd2[db].y, expf(lrelu(s1v + d1v)));
        } else if (e < E2) {
            int sa, da;
            edge2(e, ei, sa, da);
            atomicAdd(&g_dd2[da].y, expf(lrelu(g_s2[sa] + g_dd2[da].x)));
        }
    } else {
        int b = bid - NBDE2;
        int g = b / DP, p = b % DP;
        int beg = g * NPERK + p * DC;
        int end = min(beg + DC, (g + 1) * NPERK);
        float dh = g_dd2[NN + g].x;
        float a0 = 0.f;
        for (int i = beg + threadIdx.x; i < end; i += 256)
            a0 += expf(lrelu(g_s2[i] + dh));
        a0 = wsum(a0);
        __shared__ float sd;
        if (threadIdx.x == 0) sd = 0.f;
        __syncthreads();
        if ((threadIdx.x & 31) == 0) atomicAdd(&sd, a0);
        __syncthreads();
        if (threadIdx.x == 0) atomicAdd(&g_dd2[NN + g].y, sd);
    }
}

// =========== merged: att output + glb aggregation (into out) ==============
#define NBT ((ET + 255) / 256)          // 1954 att blocks
__global__ void k_g2out(const int* __restrict__ ei, float* __restrict__ out) {
    int bid = blockIdx.x;
    if (bid < NBT) {
        int e = bid * 256 + threadIdx.x; if (e >= ET) return;
        int s, d; edge_sd(e, ei, s, d);
        float2 dd = g_dd2[d];
        float w = expf(lrelu(g_s2[s] + dd.x)) / (dd.y + 1e-16f);
        out[2048 + e]          = (float)s;
        out[2048 + ET + e]     = (float)d;
        out[2048 + 2 * ET + e] = w;
    } else {
        int q = (bid - NBT) * 4 + (threadIdx.x >> 6);
        int g = q / AP, p = q % AP;
        int beg = g * NPERK + p * AC;
        int end = min(beg + AC, (g + 1) * NPERK);
        int c = threadIdx.x & 63;
        float2 ddg = g_dd2[NN + g];
        float dh  = ddg.x;
        float den = ddg.y + 1e-16f;
        float acc = 0.f;
        int s = beg;
        for (; s + 3 < end; s += 4) {
            float w0 = expf(lrelu(g_s2[s]     + dh)) / den;
            float w1 = expf(lrelu(g_s2[s + 1] + dh)) / den;
            float w2 = expf(lrelu(g_s2[s + 2] + dh)) / den;
            float w3 = expf(lrelu(g_s2[s + 3] + dh)) / den;
            float x0 = g_xh2[s * 64 + c];
            float x1 = g_xh2[(s + 1) * 64 + c];
            float x2 = g_xh2[(s + 2) * 64 + c];
            float x3 = g_xh2[(s + 3) * 64 + c];
            acc += w0 * x0 + w1 * x1 + w2 * x2 + w3 * x3;
        }
        for (; s < end; s++)
            acc += expf(lrelu(g_s2[s] + dh)) / den * g_xh2[s * 64 + c];
        if (p == 0) {   // glb self-loop
            float w = expf(lrelu(g_s2[NN + g] + dh)) / den;
            acc += w * g_xh2[(NN + g) * 64 + c];
        }
        atomicAdd(&out[g * 64 + c], acc);
    }
}

// ---------------- launch ----------------
extern "C" void kernel_launch(void* const* d_in, const int* in_sizes, int n_in,
                              void* d_out, int out_size)
{
    const float* feat = (const float*)d_in[0];
    const int*   ei   = (const int*)  d_in[1];
    const float* ltg  = (const float*)d_in[4];
    const float* ltb  = (const float*)d_in[5];
    const float* ltW  = (const float*)d_in[6];
    const float* ltWb = (const float*)d_in[7];
    const float* lvg  = (const float*)d_in[8];
    const float* lvb  = (const float*)d_in[9];
    const float* lvW  = (const float*)d_in[10];
    const float* lvWb = (const float*)d_in[11];
    const float* gW   = (const float*)d_in[12];
    const float* gb   = (const float*)d_in[13];
    const float* glbn = (const float*)d_in[14];
    const float* W1   = (const float*)d_in[15];
    const float* as1  = (const float*)d_in[16];
    const float* ad1  = (const float*)d_in[17];
    const float* b1   = (const float*)d_in[18];
    const float* W2   = (const float*)d_in[19];
    const float* as2  = (const float*)d_in[20];
    const float* ad2  = (const float*)d_in[21];
    const float* b2   = (const float*)d_in[22];
    float* out = (float*)d_out;

    k_fuse   <<<65, 128>>>(ltW, ltWb, lvW, lvWb, gW, gb, glbn, W1, as1, ad1);
    k_nodeg1 <<<NT / 32, 128>>>(feat, ltg, ltb, lvg, lvb, as1, ad1);
    k_g1den  <<<NBDE2 + BB * DP, 256>>>(ei);
    k_g1agg  <<<NBAE4 + BB * AP / 2, 256>>>(ei);
    k_g2pre  <<<NT / 64, 256>>>(b1, W2, as2, ad2, b2, out);
    k_g2den  <<<NBDE2 + BB * DP, 256>>>(ei);
    k_g2out  <<<NBT + BB * AP / 4, 256>>>(ei, out);
}

// round 17
// speedup vs baseline: 1.0382x; 1.0382x over previous
#include <cuda_runtime.h>
#include <math.h>

#define NN    100000
#define BB    32
#define NPERK 3125
#define NT    100032          // NN + BB   (NN % 32 == 0, NT % 64 == 0)
#define EE    200000
#define ET    500032          // EE + 2*NN + NT
#define E2    (EE + NN)       // light edges (att indexing only)

// ---------------- scratch (device globals; no allocations) ----------------
__device__ __align__(16) float g_xh1 [NT * 128];
__device__ __align__(16) float g_agg1[NT * 128];   // random-edge sums (self+glb added in g2pre)
__device__ __align__(16) float g_xh2 [NT * 64];
__device__ float g_s1[NT * 2], g_d1[NT * 2], g_den1[NT * 2];
__device__ float g_s2[NT];
__device__ __align__(8) float2 g_dd2[NT];          // {d2, den2}
// fused feat->xh1 weights (precomputed each launch by k_fuse)
__device__ __align__(16) float g_F [64 * 128];
__device__ __align__(16) float g_bF[128];
__device__ __align__(16) float g_gx[128];          // glb-node xh1 row (shared by all 32)
__device__ float g_gl[6];                          // glb s1h0,s1h1,d1h0,d1h1,den1h0,den1h1

// ---------------- helpers ----------------
typedef unsigned long long u64;
__device__ __forceinline__ u64 pk2(float lo, float hi) {
    u64 r; asm("mov.b64 %0,{%1,%2};" : "=l"(r) : "f"(lo), "f"(hi)); return r;
}
__device__ __forceinline__ u64 bc2(float v) { return pk2(v, v); }
__device__ __forceinline__ void upk2(u64 v, float& lo, float& hi) {
    asm("mov.b64 {%0,%1},%2;" : "=f"(lo), "=f"(hi) : "l"(v));
}
__device__ __forceinline__ void fma2(u64& d, u64 a, u64 b) {
    asm("fma.rn.f32x2 %0, %1, %2, %0;" : "+l"(d) : "l"(a), "l"(b));
}
__device__ __forceinline__ float lrelu(float a) { return a > 0.f ? a : 0.2f * a; }

__device__ __forceinline__ float wsum(float v) {
    #pragma unroll
    for (int o = 16; o; o >>= 1) v += __shfl_xor_sync(0xffffffffu, v, o);
    return v;
}
__device__ __forceinline__ float hsum16(float v) {
    #pragma unroll
    for (int o = 8; o; o >>= 1) v += __shfl_xor_sync(0xffffffffu, v, o);
    return v;
}

// full edge list (for att output): src=[ei0,glb,ids,loop], dst=[ei1,ids,glb,loop]
__device__ __forceinline__ void edge_sd(int e, const int* __restrict__ ei, int& s, int& d) {
    if (e < EE)             { s = ei[e];               d = ei[EE + e]; }
    else if (e < EE + NN)   { int i = e - EE;          s = NN + i / NPERK; d = i; }
    else if (e < EE + 2*NN) { int i = e - EE - NN;     s = i; d = NN + i / NPERK; }
    else                    { int i = e - EE - 2*NN;   s = i; d = i; }
}
// light edges (att only): random + glb->node
__device__ __forceinline__ void edge2(int e, const int* __restrict__ ei, int& s, int& d) {
    if (e < EE) { s = ei[e]; d = ei[EE + e]; }
    else        { int i = e - EE; s = NN + i / NPERK; d = i; }
}

// =========== weight fusion: F = fold(ltW/lvW, gW, W1), bF, glb row ========
__global__ void k_fuse(const float* __restrict__ ltW, const float* __restrict__ ltWb,
                       const float* __restrict__ lvW, const float* __restrict__ lvWb,
                       const float* __restrict__ gW,  const float* __restrict__ gb,
                       const float* __restrict__ glbn, const float* __restrict__ W1,
                       const float* __restrict__ asr, const float* __restrict__ ads)
{
    int b = blockIdx.x, c = threadIdx.x;
    if (b < 64) {
        __shared__ float H[64];
        if (c < 64) {
            float acc = 0.f;
            if (b < 39) { for (int m = 0; m < 64; m++) acc += ltW[b * 64 + m] * gW[(64 + m) * 64 + c]; }
            else { int j = b - 39; for (int m = 0; m < 64; m++) acc += lvW[j * 64 + m] * gW[m * 64 + c]; }
            H[c] = acc;
        }
        __syncthreads();
        float f = 0.f;
        for (int a = 0; a < 64; a++) f += H[a] * W1[a * 128 + c];
        g_F[b * 128 + c] = f;
    } else {
        __shared__ float Hb[64], GX[128];
        if (c < 64) {
            float acc = gb[c];
            for (int m = 0; m < 64; m++) acc += lvWb[m] * gW[m * 64 + c];
            for (int m = 0; m < 64; m++) acc += ltWb[m] * gW[(64 + m) * 64 + c];
            Hb[c] = acc;
        }
        __syncthreads();
        float bf = 0.f, gx = 0.f;
        for (int a = 0; a < 64; a++) {
            bf += Hb[a] * W1[a * 128 + c];
            gx += glbn[a] * W1[a * 128 + c];
        }
        g_bF[c] = bf;
        g_gx[c] = gx;
        GX[c] = gx;
        __syncthreads();
        if (c < 32) {
            int l = c;
            float4 av = ((const float4*)asr)[l];
            float4 dv = ((const float4*)ads)[l];
            float ps = GX[4*l] * av.x + GX[4*l+1] * av.y + GX[4*l+2] * av.z + GX[4*l+3] * av.w;
            float pd = GX[4*l] * dv.x + GX[4*l+1] * dv.y + GX[4*l+2] * dv.z + GX[4*l+3] * dv.w;
            ps = hsum16(ps); pd = hsum16(pd);
            if (l == 0)  { g_gl[0] = ps; g_gl[2] = pd; g_gl[4] = expf(lrelu(ps + pd)); }
            if (l == 16) { g_gl[1] = ps; g_gl[3] = pd; g_gl[5] = expf(lrelu(ps + pd)); }
        }
    }
}

// =========== fused node pipeline: LN -> xh1 = LNfeat @ F + bF =============
// den1 base = exp(self) + exp(glb->node edge); zeroes agg1 rows
#define SF 34
__global__ void __launch_bounds__(128)
k_nodeg1(const float* __restrict__ feat,
         const float* __restrict__ ltg, const float* __restrict__ ltb,
         const float* __restrict__ lvg, const float* __restrict__ lvb,
         const float* __restrict__ asr, const float* __restrict__ ads)
{
    __shared__ float shF[64 * SF];
    int tid = threadIdx.x, wp = tid >> 5, l = tid & 31;
    int n0 = blockIdx.x * 32;
    int nb = wp * 8;

    // zero agg1 rows for this block's 32 nodes (random-edge base)
    {
        float4 z = make_float4(0.f, 0.f, 0.f, 0.f);
        float4* dst = (float4*)(g_agg1 + n0 * 128);
        #pragma unroll
        for (int t = 0; t < 8; t++) dst[t * 128 + tid] = z;
    }

    if (n0 >= NN) {                    // last block: pure glb nodes
        for (int t = tid; t < 32 * 32; t += 128) {
            int nl = t >> 5, l4 = t & 31;
            ((float4*)(g_xh1 + (NN + nl) * 128))[l4] = ((const float4*)g_gx)[l4];
        }
        if (tid < 32) {
            int n = NN + tid;
            g_s1[2*n] = g_gl[0]; g_s1[2*n+1] = g_gl[1];
            g_d1[2*n] = g_gl[2]; g_d1[2*n+1] = g_gl[3];
            g_den1[2*n] = g_gl[4]; g_den1[2*n+1] = g_gl[5];
        }
        return;
    }

    for (int t = tid; t < 32 * 64; t += 128) {
        int nl = t >> 6, c = t & 63;
        shF[c * SF + nl] = feat[(n0 + nl) * 64 + c];
    }
    __syncthreads();

    // ---- layernorm per node (round-6 wsum order), 8 nodes/warp ----
    #pragma unroll
    for (int i = 0; i < 8; i++) {
        int nl = nb + i;
        float f0 = shF[l * SF + nl];
        float f1 = shF[(32 + l) * SF + nl];
        int k1 = l + 32;
        float ts = f0      + (k1 < 39 ? f1      : 0.f);
        float tq = f0 * f0 + (k1 < 39 ? f1 * f1 : 0.f);
        float vs = (k1 >= 39 ? f1      : 0.f);
        float vq = (k1 >= 39 ? f1 * f1 : 0.f);
        ts = wsum(ts); tq = wsum(tq); vs = wsum(vs); vq = wsum(vq);
        float mt = ts * (1.f / 39.f);
        float rt = rsqrtf(tq * (1.f / 39.f) - mt * mt + 1e-5f);
        float mv = vs * (1.f / 25.f);
        float rv = rsqrtf(vq * (1.f / 25.f) - mv * mv + 1e-5f);
        float a = (f0 - mt) * rt * ltg[l] + ltb[l];
        float b;
        if (k1 < 39) b = (f1 - mt) * rt * ltg[k1] + ltb[k1];
        else { int j = k1 - 39; b = (f1 - mv) * rv * lvg[j] + lvb[j]; }
        shF[l * SF + nl] = a; shF[k1 * SF + nl] = b;
    }
    __syncwarp();

    // ---- xh1 = LNfeat @ F + bF; logits + den1 base (self + glb edge) ----
    {
        float4 bf = ((const float4*)g_bF)[l];
        u64 ox[4], oy[4], oz[4], ow[4];
        #pragma unroll
        for (int q = 0; q < 4; q++) {
            ox[q] = bc2(bf.x); oy[q] = bc2(bf.y);
            oz[q] = bc2(bf.z); ow[q] = bc2(bf.w);
        }
        for (int k = 0; k < 64; k++) {
            float4 w = ((const float4*)(g_F + k * 128))[l];
            u64 w0 = bc2(w.x), w1 = bc2(w.y), w2 = bc2(w.z), w3 = bc2(w.w);
            #pragma unroll
            for (int q = 0; q < 4; q++) {
                u64 sp = *(const u64*)&shF[k * SF + nb + 2 * q];
                fma2(ox[q], sp, w0); fma2(oy[q], sp, w1);
                fma2(oz[q], sp, w2); fma2(ow[q], sp, w3);
            }
        }
        float4 av = ((const float4*)asr)[l];
        float4 dv = ((const float4*)ads)[l];
        float gls0 = g_gl[0], gls1 = g_gl[1];
        #pragma unroll
        for (int i = 0; i < 8; i++) {
            int q = i >> 1;
            float x0, x1, y0, y1, z0, z1, u0, u1;
            upk2(ox[q], x0, x1); upk2(oy[q], y0, y1);
            upk2(oz[q], z0, z1); upk2(ow[q], u0, u1);
            float a = (i & 1) ? x1 : x0;
            float b = (i & 1) ? y1 : y0;
            float c = (i & 1) ? z1 : z0;
            float e = (i & 1) ? u1 : u0;
            int n = n0 + nb + i;
            float ps = hsum16(a * av.x + b * av.y + c * av.z + e * av.w);
            float pd = hsum16(a * dv.x + b * dv.y + c * dv.z + e * dv.w);
            ((float4*)(g_xh1 + n * 128))[l] = make_float4(a, b, c, e);
            if (l == 0) {        // head 0
                g_s1[2 * n] = ps; g_d1[2 * n] = pd;
                g_den1[2 * n] = expf(lrelu(ps + pd)) + expf(lrelu(gls0 + pd));
            }
            if (l == 16) {       // head 1
                g_s1[2 * n + 1] = ps; g_d1[2 * n + 1] = pd;
                g_den1[2 * n + 1] = expf(lrelu(ps + pd)) + expf(lrelu(gls1 + pd));
            }
        }
    }
}

// =========== GAT1 denominator: random edges (2/thread) + glb ==============
#define NBDE ((EE + 511) / 512)         // 391 edge blocks
#define DP 32
#define DC ((NPERK + DP - 1) / DP)      // 98
__global__ void k_g1den(const int* __restrict__ ei) {
    int bid = blockIdx.x;
    if (bid < NBDE) {
        int e = bid * 512 + threadIdx.x;
        if (e + 256 < EE) {
            int sa = ei[e],       da = ei[EE + e];
            int sb = ei[e + 256], db = ei[EE + e + 256];
            float2 sva = *(const float2*)&g_s1[2 * sa];
            float2 dva = *(const float2*)&g_d1[2 * da];
            float2 svb = *(const float2*)&g_s1[2 * sb];
            float2 dvb = *(const float2*)&g_d1[2 * db];
            atomicAdd((float2*)&g_den1[2 * da],
                      make_float2(expf(lrelu(sva.x + dva.x)), expf(lrelu(sva.y + dva.y))));
            atomicAdd((float2*)&g_den1[2 * db],
                      make_float2(expf(lrelu(svb.x + dvb.x)), expf(lrelu(svb.y + dvb.y))));
        } else if (e < EE) {
            int sa = ei[e], da = ei[EE + e];
            float2 sva = *(const float2*)&g_s1[2 * sa];
            float2 dva = *(const float2*)&g_d1[2 * da];
            atomicAdd((float2*)&g_den1[2 * da],
                      make_float2(expf(lrelu(sva.x + dva.x)), expf(lrelu(sva.y + dva.y))));
        }
    } else {
        int b = bid - NBDE;
        int g = b / DP, p = b % DP;
        int beg = g * NPERK + p * DC;
        int end = min(beg + DC, (g + 1) * NPERK);
        float dh0 = g_d1[(NN + g) * 2], dh1 = g_d1[(NN + g) * 2 + 1];
        float a0 = 0.f, a1 = 0.f;
        for (int i = beg + threadIdx.x; i < end; i += 256) {
            a0 += expf(lrelu(g_s1[2 * i]     + dh0));
            a1 += expf(lrelu(g_s1[2 * i + 1] + dh1));
        }
        a0 = wsum(a0); a1 = wsum(a1);
        __shared__ float sd[2];
        if (threadIdx.x < 2) sd[threadIdx.x] = 0.f;
        __syncthreads();
        if ((threadIdx.x & 31) == 0) { atomicAdd(&sd[0], a0); atomicAdd(&sd[1], a1); }
        __syncthreads();
        if (threadIdx.x < 2) atomicAdd(&g_den1[(NN + g) * 2 + threadIdx.x], sd[threadIdx.x]);
    }
}

// =========== GAT1 aggregation: random edges (2/warp) + glb ================
#define NBAE (EE / 16)                  // 12500 exact
#define AP 64
#define AC ((NPERK + AP - 1) / AP)      // 49
__global__ void k_g1agg(const int* __restrict__ ei) {
    int bid = blockIdx.x;
    if (bid < NBAE) {
        int wp = threadIdx.x >> 5, l = threadIdx.x & 31;
        int h = l >> 4;
        int e0 = (bid * 8 + wp) * 2;
        int s0 = ei[e0],     d0 = ei[EE + e0];
        int s1 = ei[e0 + 1], d1 = ei[EE + e0 + 1];
        float w0 = expf(lrelu(g_s1[s0 * 2 + h] + g_d1[d0 * 2 + h])) / (g_den1[d0 * 2 + h] + 1e-16f);
        float w1 = expf(lrelu(g_s1[s1 * 2 + h] + g_d1[d1 * 2 + h])) / (g_den1[d1 * 2 + h] + 1e-16f);
        float4 a = ((const float4*)g_xh1)[s0 * 32 + l];
        float4 b = ((const float4*)g_xh1)[s1 * 32 + l];
        a.x *= w0; a.y *= w0; a.z *= w0; a.w *= w0;
        b.x *= w1; b.y *= w1; b.z *= w1; b.w *= w1;
        atomicAdd(((float4*)g_agg1) + d0 * 32 + l, a);
        atomicAdd(((float4*)g_agg1) + d1 * 32 + l, b);
    } else {
        int q = (bid - NBAE) * 2 + (threadIdx.x >> 7);
        int g = q / AP, p = q % AP;
        int beg = g * NPERK + p * AC;
        int end = min(beg + AC, (g + 1) * NPERK);
        int c = threadIdx.x & 127, h = c >> 6;
        float dh  = g_d1[(NN + g) * 2 + h];
        float den = g_den1[(NN + g) * 2 + h] + 1e-16f;
        float acc = 0.f;
        int s = beg;
        for (; s + 3 < end; s += 4) {
            float w0 = expf(lrelu(g_s1[2 * s + h]     + dh)) / den;
            float w1 = expf(lrelu(g_s1[2 * (s+1) + h] + dh)) / den;
            float w2 = expf(lrelu(g_s1[2 * (s+2) + h] + dh)) / den;
            float w3 = expf(lrelu(g_s1[2 * (s+3) + h] + dh)) / den;
            float x0 = g_xh1[s * 128 + c];
            float x1 = g_xh1[(s+1) * 128 + c];
            float x2 = g_xh1[(s+2) * 128 + c];
            float x3 = g_xh1[(s+3) * 128 + c];
            acc += w0 * x0 + w1 * x1 + w2 * x2 + w3 * x3;
        }
        for (; s < end; s++)
            acc += expf(lrelu(g_s1[2 * s + h] + dh)) / den * g_xh1[s * 128 + c];
        atomicAdd(&g_agg1[(NN + g) * 128 + c], acc);
    }
}

// =========== GAT2 transform: + self & glb-edge terms, f32x2 ===============
#define SH 66
__global__ void __launch_bounds__(256)
k_g2pre(const float* __restrict__ b1, const float* __restrict__ W2,
        const float* __restrict__ as2, const float* __restrict__ ad2,
        const float* __restrict__ b2, float* __restrict__ out)
{
    __shared__ float shH[128 * SH];    // relu(agg + wself*xh1 + wglb*gx + b1) [ch][node]
    __shared__ float shWS[128];        // w_self per (node, head)
    __shared__ float shWG[128];        // w_glb  per (node, head)
    __shared__ float shGX[128];        // glb xh1 row
    int tid = threadIdx.x, wp = tid >> 5, l = tid & 31;
    int n0 = blockIdx.x * 64;
    int nb = wp * 8;

    if (blockIdx.x == 0) {             // seed out[0:2048] = b2 (g2out adds into it)
        for (int i = tid; i < BB * 64; i += 256) out[i] = b2[i & 63];
    }

    if (tid < 128) {
        shGX[tid] = g_gx[tid];
        int node = tid >> 1, h = tid & 1;
        int gn = n0 + node;
        float d1v = g_d1[2 * gn + h];
        float deninv = 1.f / (g_den1[2 * gn + h] + 1e-16f);
        shWS[tid] = expf(lrelu(g_s1[2 * gn + h] + d1v)) * deninv;
        shWG[tid] = (gn < NN) ? expf(lrelu(g_gl[h] + d1v)) * deninv : 0.f;
    }
    __syncthreads();

    for (int t = tid; t < 64 * 128; t += 256) {
        int nl = t >> 7, c = t & 127;
        int gn = n0 + nl;
        int hh = c >> 6;
        float v = fmaxf(g_agg1[gn * 128 + c]
                        + shWS[nl * 2 + hh] * g_xh1[gn * 128 + c]
                        + shWG[nl * 2 + hh] * shGX[c]
                        + b1[c], 0.f);
        shH[c * SH + nl] = v;
    }
    __syncthreads();

    u64 oa[4], ob[4];
    #pragma unroll
    for (int q = 0; q < 4; q++) { oa[q] = 0; ob[q] = 0; }
    for (int k = 0; k < 128; k++) {
        float2 w = ((const float2*)(W2 + k * 64))[l];
        u64 wx = bc2(w.x), wy = bc2(w.y);
        #pragma unroll
        for (int q = 0; q < 4; q++) {
            u64 sp = *(const u64*)&shH[k * SH + nb + 2 * q];
            fma2(oa[q], sp, wx); fma2(ob[q], sp, wy);
        }
    }
    float2 sa = ((const float2*)as2)[l];
    float2 da = ((const float2*)ad2)[l];
    #pragma unroll
    for (int i = 0; i < 8; i++) {
        int q = i >> 1;
        float a0, a1, b0v, b1v;
        upk2(oa[q], a0, a1); upk2(ob[q], b0v, b1v);
        float a = (i & 1) ? a1 : a0;
        float b = (i & 1) ? b1v : b0v;
        int n = n0 + nb + i;
        float ps = wsum(a * sa.x + b * sa.y);
        float pd = wsum(a * da.x + b * da.y);
        ((float2*)(g_xh2 + n * 64))[l] = make_float2(a, b);
        if (l == 0) {
            g_s2[n] = ps;
            g_dd2[n] = make_float2(pd, expf(lrelu(ps + pd)));  // {d2, den2 self base}
        }
    }
}

// =========== GAT2 denominator: edge (2/thread, incl glb->node) + glb ======
#define NBDE2 ((E2 + 511) / 512)        // 586 edge blocks
__global__ void k_g2den(const int* __restrict__ ei) {
    int bid = blockIdx.x;
    if (bid < NBDE2) {
        int e = bid * 512 + threadIdx.x;
        if (e + 256 < E2) {
            int sa, da, sb, db;
            edge2(e,       ei, sa, da);
            edge2(e + 256, ei, sb, db);
            float s0 = g_s2[sa], d0 = g_dd2[da].x;
            float s1v = g_s2[sb], d1v = g_dd2[db].x;
            atomicAdd(&g_dd2[da].y, expf(lrelu(s0 + d0)));
            atomicAdd(&g_dd2[db].y, expf(lrelu(s1v + d1v)));
        } else if (e < E2) {
            int sa, da;
            edge2(e, ei, sa, da);
            atomicAdd(&g_dd2[da].y, expf(lrelu(g_s2[sa] + g_dd2[da].x)));
        }
    } else {
        int b = bid - NBDE2;
        int g = b / DP, p = b % DP;
        int beg = g * NPERK + p * DC;
        int end = min(beg + DC, (g + 1) * NPERK);
        float dh = g_dd2[NN + g].x;
        float a0 = 0.f;
        for (int i = beg + threadIdx.x; i < end; i += 256)
            a0 += expf(lrelu(g_s2[i] + dh));
        a0 = wsum(a0);
        __shared__ float sd;
        if (threadIdx.x == 0) sd = 0.f;
        __syncthreads();
        if ((threadIdx.x & 31) == 0) atomicAdd(&sd, a0);
        __syncthreads();
        if (threadIdx.x == 0) atomicAdd(&g_dd2[NN + g].y, sd);
    }
}

// =========== merged: att output + glb aggregation (into out) ==============
#define NBT ((ET + 255) / 256)          // 1954 att blocks
__global__ void k_g2out(const int* __restrict__ ei, float* __restrict__ out) {
    int bid = blockIdx.x;
    if (bid < NBT) {
        int e = bid * 256 + threadIdx.x; if (e >= ET) return;
        int s, d; edge_sd(e, ei, s, d);
        float2 dd = g_dd2[d];
        float w = expf(lrelu(g_s2[s] + dd.x)) / (dd.y + 1e-16f);
        out[2048 + e]          = (float)s;
        out[2048 + ET + e]     = (float)d;
        out[2048 + 2 * ET + e] = w;
    } else {
        int q = (bid - NBT) * 4 + (threadIdx.x >> 6);
        int g = q / AP, p = q % AP;
        int beg = g * NPERK + p * AC;
        int end = min(beg + AC, (g + 1) * NPERK);
        int c = threadIdx.x & 63;
        float2 ddg = g_dd2[NN + g];
        float dh  = ddg.x;
        float den = ddg.y + 1e-16f;
        float acc = 0.f;
        int s = beg;
        for (; s + 3 < end; s += 4) {
            float w0 = expf(lrelu(g_s2[s]     + dh)) / den;
            float w1 = expf(lrelu(g_s2[s + 1] + dh)) / den;
            float w2 = expf(lrelu(g_s2[s + 2] + dh)) / den;
            float w3 = expf(lrelu(g_s2[s + 3] + dh)) / den;
            float x0 = g_xh2[s * 64 + c];
            float x1 = g_xh2[(s + 1) * 64 + c];
            float x2 = g_xh2[(s + 2) * 64 + c];
            float x3 = g_xh2[(s + 3) * 64 + c];
            acc += w0 * x0 + w1 * x1 + w2 * x2 + w3 * x3;
        }
        for (; s < end; s++)
            acc += expf(lrelu(g_s2[s] + dh)) / den * g_xh2[s * 64 + c];
        if (p == 0) {   // glb self-loop
            float w = expf(lrelu(g_s2[NN + g] + dh)) / den;
            acc += w * g_xh2[(NN + g) * 64 + c];
        }
        atomicAdd(&out[g * 64 + c], acc);
    }
}

// ---------------- launch ----------------
extern "C" void kernel_launch(void* const* d_in, const int* in_sizes, int n_in,
                              void* d_out, int out_size)
{
    const float* feat = (const float*)d_in[0];
    const int*   ei   = (const int*)  d_in[1];
    const float* ltg  = (const float*)d_in[4];
    const float* ltb  = (const float*)d_in[5];
    const float* ltW  = (const float*)d_in[6];
    const float* ltWb = (const float*)d_in[7];
    const float* lvg  = (const float*)d_in[8];
    const float* lvb  = (const float*)d_in[9];
    const float* lvW  = (const float*)d_in[10];
    const float* lvWb = (const float*)d_in[11];
    const float* gW   = (const float*)d_in[12];
    const float* gb   = (const float*)d_in[13];
    const float* glbn = (const float*)d_in[14];
    const float* W1   = (const float*)d_in[15];
    const float* as1  = (const float*)d_in[16];
    const float* ad1  = (const float*)d_in[17];
    const float* b1   = (const float*)d_in[18];
    const float* W2   = (const float*)d_in[19];
    const float* as2  = (const float*)d_in[20];
    const float* ad2  = (const float*)d_in[21];
    const float* b2   = (const float*)d_in[22];
    float* out = (float*)d_out;

    k_fuse   <<<65, 128>>>(ltW, ltWb, lvW, lvWb, gW, gb, glbn, W1, as1, ad1);
    k_nodeg1 <<<NT / 32, 128>>>(feat, ltg, ltb, lvg, lvb, as1, ad1);
    k_g1den  <<<NBDE + BB * DP, 256>>>(ei);
    k_g1agg  <<<NBAE + BB * AP / 2, 256>>>(ei);
    k_g2pre  <<<NT / 64, 256>>>(b1, W2, as2, ad2, b2, out);
    k_g2den  <<<NBDE2 + BB * DP, 256>>>(ei);
    k_g2out  <<<NBT + BB * AP / 4, 256>>>(ei, out);
}